// round 1
// baseline (speedup 1.0000x reference)
#include <cuda_runtime.h>

// Problem constants (fixed by the reference)
#define NLAT 181
#define NLON 360
#define CIN  128
#define COUT 128
#define KS   3
#define BSZ  2
#define CHW  (NLAT * NLON)        // 65160
#define CK   (CIN * KS)           // 384
#define PT   64                   // p-tile per block
#define NPT  6                    // ceil(360/64)
#define MAXNZ (1 << 20)

// Scratch (device globals: allocation-free per harness rules)
__device__ int   g_ofs[NLAT * KS + 2];
__device__ int   g_pos[MAXNZ];     // (lat << 16) | lon
__device__ float g_sval[MAXNZ];    // psi_val * quad_weight[lat]

// ---------------------------------------------------------------------------
// Setup: fold quadrature weights into psi values, pack coords, and compute
// per-(t,k) segment offsets. Entries are generated with t outer / k inner, so
// key(i) = (seg%181)*3 + seg/181 is monotone non-decreasing -> binary search.
// ---------------------------------------------------------------------------
__global__ void setup_kernel(const int* __restrict__ seg,
                             const int* __restrict__ lat,
                             const int* __restrict__ lon,
                             const float* __restrict__ vals,
                             const float* __restrict__ qw,
                             int nnz) {
    int i = blockIdx.x * blockDim.x + threadIdx.x;
    if (i < nnz && i < MAXNZ) {
        int la = lat[i];
        g_pos[i]  = (la << 16) | lon[i];
        g_sval[i] = vals[i] * qw[la];
    }
    if (blockIdx.x == 0) {
        for (int j = threadIdx.x; j <= NLAT * KS; j += blockDim.x) {
            int lo = 0, hi = nnz;
            while (lo < hi) {
                int m = (lo + hi) >> 1;
                int sgv = seg[m];
                int key = (sgv % NLAT) * KS + (sgv / NLAT);
                if (key < j) lo = m + 1; else hi = m;
            }
            g_ofs[j] = lo;
        }
    }
}

// ---------------------------------------------------------------------------
// Fused main kernel. Block = (p-tile, t, b). 256 threads.
// Stage 1: gather s[(c*3+k), p] into smem (384 x 64 fp32 = 96 KB).
//   Warp w owns channels [16w, 16w+16); lanes = p within a 32-wide subtile.
//   x loads: 32 consecutive floats per warp-LDG (coalesced), 16-way c-unroll.
// Stage 2: out[128f x 64p] = W[128x384] @ s[384x64] + bias, 8f x 4p per thread.
// ---------------------------------------------------------------------------
__global__ void __launch_bounds__(256, 2)
disco_kernel(const float* __restrict__ x,
             const float* __restrict__ weight,
             const float* __restrict__ bias,
             float* __restrict__ out) {
    extern __shared__ float smem_s[];   // [CK][PT]

    const int tid  = threadIdx.x;
    const int warp = tid >> 5;
    const int lane = tid & 31;

    // Pole-first t order: heaviest (polar) rows launch in the first wave.
    const int yb = blockIdx.y;
    const int t  = (yb & 1) ? (NLAT - 1 - (yb >> 1)) : (yb >> 1);
    const int b  = blockIdx.z;
    const int p0 = blockIdx.x * PT;

    const int cbase = warp * 16;
    const float* xb = x + (size_t)(b * CIN + cbase) * CHW;

    // ---------------- Stage 1: gather ----------------
    #pragma unroll
    for (int sp = 0; sp < 2; sp++) {
        int p  = p0 + sp * 32 + lane;          // may exceed 359 in last tile
        int pm = (p >= NLON) ? p - NLON : p;   // harmless clamp; store-side guarded
        #pragma unroll
        for (int k = 0; k < KS; k++) {
            const int e0 = g_ofs[t * KS + k];
            const int e1 = g_ofs[t * KS + k + 1];
            float acc[16];
            #pragma unroll
            for (int j = 0; j < 16; j++) acc[j] = 0.f;
            for (int e = e0; e < e1; e++) {
                const int   pos = g_pos[e];      // warp-uniform
                const float sv  = g_sval[e];     // warp-uniform
                const int la = pos >> 16;
                const int lo = pos & 0xffff;
                int lp = lo + pm;
                if (lp >= NLON) lp -= NLON;
                const int idx = la * NLON + lp;
                #pragma unroll
                for (int j = 0; j < 16; j++)
                    acc[j] += sv * __ldg(xb + (size_t)j * CHW + idx);
            }
            #pragma unroll
            for (int j = 0; j < 16; j++)
                smem_s[((cbase + j) * KS + k) * PT + sp * 32 + lane] = acc[j];
        }
    }
    __syncthreads();

    // ---------------- Stage 2: GEMM out = W @ s ----------------
    // thread (tf, tp): tf = tid>>4 in [0,16) -> 8 f's; tp = tid&15 -> 4 p's.
    const int tp = tid & 15;
    const int tf = tid >> 4;

    float acc2[8][4];
    #pragma unroll
    for (int i = 0; i < 8; i++) {
        const float bv = __ldg(bias + tf * 8 + i);
        #pragma unroll
        for (int j = 0; j < 4; j++) acc2[i][j] = bv;
    }

    // s rows are ordered (c*3 + k), matching weight's (c,k) minor layout.
    #pragma unroll 4
    for (int r = 0; r < CK; r++) {
        float sv[4];
        #pragma unroll
        for (int j = 0; j < 4; j++) sv[j] = smem_s[r * PT + tp + 16 * j];
        #pragma unroll
        for (int i = 0; i < 8; i++) {
            const float wv = __ldg(weight + (size_t)(tf * 8 + i) * CK + r);
            #pragma unroll
            for (int j = 0; j < 4; j++) acc2[i][j] += wv * sv[j];
        }
    }

    #pragma unroll
    for (int i = 0; i < 8; i++) {
        const int f = tf * 8 + i;
        float* ob = out + (size_t)((b * COUT + f) * NLAT + t) * NLON;
        #pragma unroll
        for (int j = 0; j < 4; j++) {
            const int p = p0 + tp + 16 * j;
            if (p < NLON) ob[p] = acc2[i][j];
        }
    }
}

// ---------------------------------------------------------------------------
// Launch. Inputs (metadata order): x, quad_weights, psi_vals, weight, bias,
// psi_seg, psi_lat, psi_lon. Output: float32 (B, COUT, NLAT, NLON).
// ---------------------------------------------------------------------------
extern "C" void kernel_launch(void* const* d_in, const int* in_sizes, int n_in,
                              void* d_out, int out_size) {
    const float* x      = (const float*)d_in[0];
    const float* qw     = (const float*)d_in[1];
    const float* vals   = (const float*)d_in[2];
    const float* weight = (const float*)d_in[3];
    const float* bias   = (const float*)d_in[4];
    const int*   seg    = (const int*)d_in[5];
    const int*   lat    = (const int*)d_in[6];
    const int*   lon    = (const int*)d_in[7];
    const int    nnz    = in_sizes[2];

    setup_kernel<<<(nnz + 255) / 256, 256>>>(seg, lat, lon, vals, qw, nnz);

    const int smem_bytes = CK * PT * sizeof(float);   // 98304
    cudaFuncSetAttribute(disco_kernel,
                         cudaFuncAttributeMaxDynamicSharedMemorySize, smem_bytes);
    dim3 grid(NPT, NLAT, BSZ);
    disco_kernel<<<grid, 256, smem_bytes>>>(x, weight, bias, (float*)d_out);
}

// round 2
// speedup vs baseline: 1.1769x; 1.1769x over previous
#include <cuda_runtime.h>

// Problem constants
#define NLAT 181
#define NLON 360
#define CIN  128
#define COUT 128
#define KS   3
#define BSZ  2
#define CHW  (NLAT * NLON)     // 65160
#define CK   (CIN * KS)        // 384
#define CKP  388               // padded row length (words) for conflict-free LDS.128
#define PT   64                // p-tile
#define NPT  6
#define SLOT 512               // max merged entries per (t, lane)

// Scratch (device globals — allocation-free)
__device__ float  g_xt[(size_t)BSZ * CHW * CIN];   // x transposed: [b][h*w][c]
__device__ int    g_mpos[NLAT * 32 * SLOT];        // (klo<<18)|(la<<9)|lo
__device__ float2 g_mw[NLAT * 32 * SLOT];          // (w_lo, w_hi), quad-weight folded
__device__ int    g_mcnt[NLAT * 32];

// ---------------------------------------------------------------------------
// Transpose x[b][c][hw] -> g_xt[b][hw][c] (channel-contiguous for LDG.128)
// ---------------------------------------------------------------------------
__global__ void transpose_kernel(const float* __restrict__ x) {
    __shared__ float tile[32][33];
    const int hw0 = blockIdx.x * 32;
    const int c0  = blockIdx.y * 32;
    const int b   = blockIdx.z;
    const int tx = threadIdx.x, ty = threadIdx.y;   // 32 x 8
    #pragma unroll
    for (int i = 0; i < 4; i++) {
        int c  = c0 + ty + i * 8;
        int hw = hw0 + tx;
        if (hw < CHW)
            tile[ty + i * 8][tx] = x[((size_t)b * CIN + c) * CHW + hw];
    }
    __syncthreads();
    #pragma unroll
    for (int i = 0; i < 4; i++) {
        int hw = hw0 + ty + i * 8;
        int c  = c0 + tx;
        if (hw < CHW)
            g_xt[((size_t)b * CHW + hw) * CIN + c] = tile[tx][ty + i * 8];
    }
}

// ---------------------------------------------------------------------------
// Merge the 3 k-segments of each output row t into unique points carrying
// (k_lo, w_lo, w_hi). Warp per t; lane handles la rows with la%32==lane.
// Entries are sorted by key=(t*3+k) then row-major (la,lo) by construction.
// ---------------------------------------------------------------------------
__global__ void merge_kernel(const int* __restrict__ seg,
                             const int* __restrict__ lat,
                             const int* __restrict__ lon,
                             const float* __restrict__ vals,
                             const float* __restrict__ qw,
                             int nnz) {
    const int gt   = (blockIdx.x * blockDim.x + threadIdx.x) >> 5;
    const int lane = threadIdx.x & 31;
    if (gt >= NLAT) return;
    const int t = gt;

    // segment boundaries via binary search on the monotone key
    int sb[4];
    #pragma unroll
    for (int k = 0; k < 4; k++) {
        const int j = t * KS + k;
        int lo = 0, hi = nnz;
        while (lo < hi) {
            int m = (lo + hi) >> 1;
            int sgv = seg[m];
            int key = (sgv % NLAT) * KS + (sgv / NLAT);
            if (key < j) lo = m + 1; else hi = m;
        }
        sb[k] = lo;
    }

    const int base = (t * 32 + lane) * SLOT;
    int cnt = 0;

    for (int la = lane; la < NLAT; la += 32) {
        // subrange [bk, ek) of each k-segment with lat == la
        int bks[3], eks[3];
        #pragma unroll
        for (int k = 0; k < 3; k++) {
            int lo = sb[k], hi = sb[k + 1];
            while (lo < hi) { int m = (lo + hi) >> 1; if (lat[m] < la) lo = m + 1; else hi = m; }
            bks[k] = lo;
            hi = sb[k + 1];
            while (lo < hi) { int m = (lo + hi) >> 1; if (lat[m] < la + 1) lo = m + 1; else hi = m; }
            eks[k] = lo;
        }
        int p0 = bks[0], p1 = bks[1], p2 = bks[2];
        const float q = qw[la];
        while (p0 < eks[0] || p1 < eks[1] || p2 < eks[2]) {
            int l0 = (p0 < eks[0]) ? lon[p0] : 0x7fffffff;
            int l1 = (p1 < eks[1]) ? lon[p1] : 0x7fffffff;
            int l2 = (p2 < eks[2]) ? lon[p2] : 0x7fffffff;
            int lm = min(l0, min(l1, l2));
            float w0 = 0.f, w1 = 0.f, w2 = 0.f;
            if (l0 == lm) { w0 = vals[p0]; p0++; }
            if (l1 == lm) { w1 = vals[p1]; p1++; }
            if (l2 == lm) { w2 = vals[p2]; p2++; }
            w0 *= q; w1 *= q; w2 *= q;
            int klo; float wl, wh;
            if      (w0 != 0.f) { klo = 0; wl = w0; wh = w1; }
            else if (w1 != 0.f) { klo = 1; wl = w1; wh = w2; }
            else if (w2 != 0.f) { klo = 2; wl = w2; wh = 0.f; }
            else continue;                  // zero-valued boundary entry
            if (cnt < SLOT) {
                g_mpos[base + cnt] = (klo << 18) | (la << 9) | lm;
                g_mw[base + cnt]   = make_float2(wl, wh);
                cnt++;
            }
        }
    }
    g_mcnt[t * 32 + lane] = cnt;
}

// ---------------------------------------------------------------------------
// Fused main kernel. Block = (p-tile 64, t, b), 256 threads = 8 warps.
// Stage 1: lanes = 4 channels each (128 c), warp covers 8 p's (2 quads).
//   Per merged entry: 4x LDG.128 + <=32 FMA.  smem layout s[p][ck] (CKP pad).
// Stage 2: out[128f x 64p] = W[128x384] @ s + bias; float4 weight + LDS.128.
// ---------------------------------------------------------------------------
__global__ void __launch_bounds__(256, 2)
disco_kernel(const float* __restrict__ weight,
             const float* __restrict__ bias,
             float* __restrict__ out) {
    extern __shared__ float smem_s[];     // [PT][CKP]
    __shared__ int s_cnt[32];

    const int tid  = threadIdx.x;
    const int warp = tid >> 5;
    const int lane = tid & 31;

    const int yb = blockIdx.y;
    const int t  = (yb & 1) ? (NLAT - 1 - (yb >> 1)) : (yb >> 1);   // pole-first
    const int b  = blockIdx.z;
    const int p0 = blockIdx.x * PT;

    if (tid < 32) s_cnt[tid] = g_mcnt[t * 32 + tid];
    __syncthreads();

    const float4* xb = (const float4*)(g_xt + (size_t)b * CHW * CIN);

    // ---------------- Stage 1 ----------------
    #pragma unroll
    for (int half = 0; half < 2; half++) {
        const int pbase = p0 + warp * 8 + half * 4;   // 4 consecutive p's
        float4 a[3][4];
        #pragma unroll
        for (int k = 0; k < 3; k++)
            #pragma unroll
            for (int q = 0; q < 4; q++)
                a[k][q] = make_float4(0.f, 0.f, 0.f, 0.f);

        for (int li = 0; li < 32; li++) {
            const int cnt  = s_cnt[li];
            const int base = (t * 32 + li) * SLOT;
            for (int e = 0; e < cnt; e++) {
                const int    pos = g_mpos[base + e];
                const float2 w   = g_mw[base + e];
                const int lo  = pos & 511;
                const int la  = (pos >> 9) & 255;
                const int klo = pos >> 18;
                const int rowb = la * NLON;
                float4 xv[4];
                #pragma unroll
                for (int q = 0; q < 4; q++) {
                    int lp = lo + pbase + q;
                    if (lp >= NLON) lp -= NLON;
                    if (lp >= NLON) lp -= NLON;
                    xv[q] = xb[(size_t)(rowb + lp) * 32 + lane];
                }
                if (klo == 0) {
                    #pragma unroll
                    for (int q = 0; q < 4; q++) {
                        a[0][q].x += w.x * xv[q].x; a[0][q].y += w.x * xv[q].y;
                        a[0][q].z += w.x * xv[q].z; a[0][q].w += w.x * xv[q].w;
                        a[1][q].x += w.y * xv[q].x; a[1][q].y += w.y * xv[q].y;
                        a[1][q].z += w.y * xv[q].z; a[1][q].w += w.y * xv[q].w;
                    }
                } else if (klo == 1) {
                    #pragma unroll
                    for (int q = 0; q < 4; q++) {
                        a[1][q].x += w.x * xv[q].x; a[1][q].y += w.x * xv[q].y;
                        a[1][q].z += w.x * xv[q].z; a[1][q].w += w.x * xv[q].w;
                        a[2][q].x += w.y * xv[q].x; a[2][q].y += w.y * xv[q].y;
                        a[2][q].z += w.y * xv[q].z; a[2][q].w += w.y * xv[q].w;
                    }
                } else {
                    #pragma unroll
                    for (int q = 0; q < 4; q++) {
                        a[2][q].x += w.x * xv[q].x; a[2][q].y += w.x * xv[q].y;
                        a[2][q].z += w.x * xv[q].z; a[2][q].w += w.x * xv[q].w;
                    }
                }
            }
        }
        // store: rows (c*3+k), c = lane*4+j  ->  rows lane*12 .. lane*12+11
        #pragma unroll
        for (int q = 0; q < 4; q++) {
            const int col = pbase - p0 + q;
            float* sp = smem_s + (size_t)col * CKP + lane * 12;
            sp[0]  = a[0][q].x; sp[1]  = a[1][q].x; sp[2]  = a[2][q].x;
            sp[3]  = a[0][q].y; sp[4]  = a[1][q].y; sp[5]  = a[2][q].y;
            sp[6]  = a[0][q].z; sp[7]  = a[1][q].z; sp[8]  = a[2][q].z;
            sp[9]  = a[0][q].w; sp[10] = a[1][q].w; sp[11] = a[2][q].w;
        }
    }
    __syncthreads();

    // ---------------- Stage 2: GEMM ----------------
    const int tp = tid & 15;       // 4 p's: tp + 16j
    const int tf = tid >> 4;       // 8 f's: tf*8 + i

    float acc2[8][4];
    #pragma unroll
    for (int i = 0; i < 8; i++) {
        const float bv = __ldg(bias + tf * 8 + i);
        #pragma unroll
        for (int j = 0; j < 4; j++) acc2[i][j] = bv;
    }

    #pragma unroll 2
    for (int r4 = 0; r4 < CK / 4; r4++) {
        float4 sv[4];
        #pragma unroll
        for (int j = 0; j < 4; j++)
            sv[j] = *(const float4*)&smem_s[(size_t)(tp + 16 * j) * CKP + r4 * 4];
        #pragma unroll
        for (int i = 0; i < 8; i++) {
            const float4 wv = __ldg((const float4*)(weight + (size_t)(tf * 8 + i) * CK + r4 * 4));
            #pragma unroll
            for (int j = 0; j < 4; j++)
                acc2[i][j] += wv.x * sv[j].x + wv.y * sv[j].y
                            + wv.z * sv[j].z + wv.w * sv[j].w;
        }
    }

    #pragma unroll
    for (int i = 0; i < 8; i++) {
        const int f = tf * 8 + i;
        float* ob = out + (size_t)((b * COUT + f) * NLAT + t) * NLON;
        #pragma unroll
        for (int j = 0; j < 4; j++) {
            const int p = p0 + tp + 16 * j;
            if (p < NLON) ob[p] = acc2[i][j];
        }
    }
}

// ---------------------------------------------------------------------------
// Launch. Inputs: x, quad_weights, psi_vals, weight, bias, psi_seg, psi_lat,
// psi_lon. Output: float32 (B, COUT, NLAT, NLON).
// ---------------------------------------------------------------------------
extern "C" void kernel_launch(void* const* d_in, const int* in_sizes, int n_in,
                              void* d_out, int out_size) {
    const float* x      = (const float*)d_in[0];
    const float* qw     = (const float*)d_in[1];
    const float* vals   = (const float*)d_in[2];
    const float* weight = (const float*)d_in[3];
    const float* bias   = (const float*)d_in[4];
    const int*   seg    = (const int*)d_in[5];
    const int*   lat    = (const int*)d_in[6];
    const int*   lon    = (const int*)d_in[7];
    const int    nnz    = in_sizes[2];

    dim3 tgrid((CHW + 31) / 32, CIN / 32, BSZ);
    transpose_kernel<<<tgrid, dim3(32, 8)>>>(x);

    merge_kernel<<<(NLAT * 32 + 127) / 128, 128>>>(seg, lat, lon, vals, qw, nnz);

    const int smem_bytes = PT * CKP * sizeof(float);   // 99328
    cudaFuncSetAttribute(disco_kernel,
                         cudaFuncAttributeMaxDynamicSharedMemorySize, smem_bytes);
    dim3 grid(NPT, NLAT, BSZ);
    disco_kernel<<<grid, 256, smem_bytes>>>(weight, bias, (float*)d_out);
}

// round 3
// speedup vs baseline: 1.6363x; 1.3903x over previous
#include <cuda_runtime.h>

// Problem constants
#define NLAT 181
#define NLON 360
#define CIN  128
#define COUT 128
#define KS   3
#define BSZ  2
#define CHW  (NLAT * NLON)     // 65160
#define CK   (CIN * KS)        // 384
#define CKP  388               // padded stage-2 row (mod 32 == 4 -> conflict-free LDS.128)
#define PT   32                // p-tile
#define NPT  12                // ceil(360/32)
#define TSLOT 2048             // max merged entries per t (pole rows ~1440)
#define CHUNK 256

// Scratch (device globals — allocation-free)
__device__ float  g_xt[(size_t)BSZ * CHW * CIN];    // x transposed: [b][h*w][c]
__device__ float4 g_rec[NLAT * TSLOT];              // {w0,w1,w2, bitcast((la<<9)|lo)}
__device__ int    g_tcnt[NLAT];

// f32x2 packed FMA helpers
__device__ __forceinline__ void fma2(unsigned long long& d,
                                     unsigned long long a,
                                     unsigned long long b) {
    asm("fma.rn.f32x2 %0, %1, %2, %0;" : "+l"(d) : "l"(a), "l"(b));
}
__device__ __forceinline__ unsigned long long pack2(float x, float y) {
    unsigned long long r;
    asm("mov.b64 %0, {%1, %2};" : "=l"(r) : "f"(x), "f"(y));
    return r;
}
union F4U { float4 f; unsigned long long u[2]; };
union U2F { unsigned long long u; float2 f; };

// ---------------------------------------------------------------------------
// Transpose x[b][c][hw] -> g_xt[b][hw][c]
// ---------------------------------------------------------------------------
__global__ void transpose_kernel(const float* __restrict__ x) {
    __shared__ float tile[32][33];
    const int hw0 = blockIdx.x * 32;
    const int c0  = blockIdx.y * 32;
    const int b   = blockIdx.z;
    const int tx = threadIdx.x, ty = threadIdx.y;   // 32 x 8
    #pragma unroll
    for (int i = 0; i < 4; i++) {
        int c  = c0 + ty + i * 8;
        int hw = hw0 + tx;
        if (hw < CHW)
            tile[ty + i * 8][tx] = x[((size_t)b * CIN + c) * CHW + hw];
    }
    __syncthreads();
    #pragma unroll
    for (int i = 0; i < 4; i++) {
        int hw = hw0 + ty + i * 8;
        int c  = c0 + tx;
        if (hw < CHW)
            g_xt[((size_t)b * CHW + hw) * CIN + c] = tile[tx][ty + i * 8];
    }
}

// ---------------------------------------------------------------------------
// Merge: one warp per t. For each unique (la, lo) of row t, emit a single
// branch-free record {w0,w1,w2,pos} (quad weight folded in). Lane handles
// la rows with la % 32 == lane; warp-scan compacts into a contiguous list.
// ---------------------------------------------------------------------------
__global__ void merge_kernel(const int* __restrict__ seg,
                             const int* __restrict__ lat,
                             const int* __restrict__ lon,
                             const float* __restrict__ vals,
                             const float* __restrict__ qw,
                             int nnz) {
    const int t    = (blockIdx.x * blockDim.x + threadIdx.x) >> 5;
    const int lane = threadIdx.x & 31;
    if (t >= NLAT) return;

    // segment boundaries via binary search on monotone key (t*3 + k)
    int sb[4];
    #pragma unroll
    for (int k = 0; k < 4; k++) {
        const int j = t * KS + k;
        int lo = 0, hi = nnz;
        while (lo < hi) {
            int m = (lo + hi) >> 1;
            int sgv = seg[m];
            int key = (sgv % NLAT) * KS + (sgv / NLAT);
            if (key < j) lo = m + 1; else hi = m;
        }
        sb[k] = lo;
    }

    // two passes: 0 = count, 1 = write
    int mycnt = 0, base = 0;
    for (int pass = 0; pass < 2; pass++) {
        int widx = 0;
        for (int la = lane; la < NLAT; la += 32) {
            int bks[3], eks[3];
            #pragma unroll
            for (int k = 0; k < 3; k++) {
                int lo = sb[k], hi = sb[k + 1];
                while (lo < hi) { int m = (lo + hi) >> 1; if (lat[m] < la) lo = m + 1; else hi = m; }
                bks[k] = lo;
                hi = sb[k + 1];
                while (lo < hi) { int m = (lo + hi) >> 1; if (lat[m] < la + 1) lo = m + 1; else hi = m; }
                eks[k] = lo;
            }
            int p0 = bks[0], p1 = bks[1], p2 = bks[2];
            const float q = qw[la];
            while (p0 < eks[0] || p1 < eks[1] || p2 < eks[2]) {
                int l0 = (p0 < eks[0]) ? lon[p0] : 0x7fffffff;
                int l1 = (p1 < eks[1]) ? lon[p1] : 0x7fffffff;
                int l2 = (p2 < eks[2]) ? lon[p2] : 0x7fffffff;
                int lm = min(l0, min(l1, l2));
                float w0 = 0.f, w1 = 0.f, w2 = 0.f;
                if (l0 == lm) { w0 = vals[p0] * q; p0++; }
                if (l1 == lm) { w1 = vals[p1] * q; p1++; }
                if (l2 == lm) { w2 = vals[p2] * q; p2++; }
                if (w0 == 0.f && w1 == 0.f && w2 == 0.f) continue;
                if (pass == 0) {
                    widx++;
                } else {
                    int idx = base + widx;
                    if (idx < TSLOT)
                        g_rec[t * TSLOT + idx] =
                            make_float4(w0, w1, w2, __int_as_float((la << 9) | lm));
                    widx++;
                }
            }
        }
        if (pass == 0) {
            mycnt = widx;
            // warp exclusive scan
            int off = mycnt;
            #pragma unroll
            for (int d = 1; d < 32; d <<= 1) {
                int v = __shfl_up_sync(0xffffffffu, off, d);
                if (lane >= d) off += v;
            }
            base = off - mycnt;
            if (lane == 31) g_tcnt[t] = min(off, TSLOT);
        }
    }
}

// ---------------------------------------------------------------------------
// Fused main kernel. Block = (p-tile 32, t, b), 256 threads = 8 warps.
// Stage 1: warp covers 4 p's; lane covers 4 channels (float4). Metadata is
//   smem-staged in 256-entry chunks; per entry: 4x LDG.128 + 24 FFMA2.
// Stage 2: out[128f x 32p] = W[128x384] @ s + bias; float4 W + LDS.128 s.
// ---------------------------------------------------------------------------
__global__ void __launch_bounds__(256, 2)
disco_kernel(const float* __restrict__ weight,
             const float* __restrict__ bias,
             float* __restrict__ out) {
    extern __shared__ float smem_s[];                       // [PT][CKP]
    float4* s_ent = (float4*)(smem_s + PT * CKP);           // [CHUNK]

    const int tid  = threadIdx.x;
    const int warp = tid >> 5;
    const int lane = tid & 31;

    const int yb = blockIdx.y;
    const int t  = (yb & 1) ? (NLAT - 1 - (yb >> 1)) : (yb >> 1);   // pole-first
    const int b  = blockIdx.z;
    const int p0 = blockIdx.x * PT;
    const int pbase = p0 + warp * 4;

    const int tcnt = g_tcnt[t];
    const float4* rec = g_rec + (size_t)t * TSLOT;
    const float4* xb  = (const float4*)(g_xt + (size_t)b * CHW * CIN);

    // ---------------- Stage 1 ----------------
    unsigned long long a2[3][4][2];
    #pragma unroll
    for (int k = 0; k < 3; k++)
        #pragma unroll
        for (int q = 0; q < 4; q++) { a2[k][q][0] = 0ull; a2[k][q][1] = 0ull; }

    for (int c0 = 0; c0 < tcnt; c0 += CHUNK) {
        const int n = min(CHUNK, tcnt - c0);
        __syncthreads();
        for (int i = tid; i < n; i += 256) s_ent[i] = __ldg(&rec[c0 + i]);
        __syncthreads();

        #pragma unroll 2
        for (int e = 0; e < n; e++) {
            const float4 r = s_ent[e];
            const int pos = __float_as_int(r.w);
            const int lo  = pos & 511;
            const int la  = pos >> 9;
            const unsigned long long w0 = pack2(r.x, r.x);
            const unsigned long long w1 = pack2(r.y, r.y);
            const unsigned long long w2 = pack2(r.z, r.z);
            const int rowb = la * NLON;
            #pragma unroll
            for (int q = 0; q < 4; q++) {
                int lp = lo + pbase + q;
                if (lp >= NLON) lp -= NLON;
                if (lp >= NLON) lp -= NLON;
                F4U xv;
                xv.f = xb[(size_t)(rowb + lp) * 32 + lane];
                fma2(a2[0][q][0], w0, xv.u[0]);
                fma2(a2[0][q][1], w0, xv.u[1]);
                fma2(a2[1][q][0], w1, xv.u[0]);
                fma2(a2[1][q][1], w1, xv.u[1]);
                fma2(a2[2][q][0], w2, xv.u[0]);
                fma2(a2[2][q][1], w2, xv.u[1]);
            }
        }
    }

    // store: channel c = lane*4+j -> row lane*12 + j*3 + k, col = local p
    #pragma unroll
    for (int q = 0; q < 4; q++) {
        const int col = warp * 4 + q;
        float* sp = smem_s + (size_t)col * CKP + lane * 12;
        #pragma unroll
        for (int k = 0; k < 3; k++) {
            U2F c0v, c1v;
            c0v.u = a2[k][q][0];
            c1v.u = a2[k][q][1];
            sp[0 * 3 + k] = c0v.f.x;
            sp[1 * 3 + k] = c0v.f.y;
            sp[2 * 3 + k] = c1v.f.x;
            sp[3 * 3 + k] = c1v.f.y;
        }
    }
    __syncthreads();

    // ---------------- Stage 2: GEMM ----------------
    const int tp = tid & 15;       // p = p0 + tp + 16j, j in {0,1}
    const int tf = tid >> 4;       // f = tf*8 + i, i in [0,8)

    float acc2[8][2];
    #pragma unroll
    for (int i = 0; i < 8; i++) {
        const float bv = __ldg(bias + tf * 8 + i);
        acc2[i][0] = bv; acc2[i][1] = bv;
    }

    #pragma unroll 2
    for (int r4 = 0; r4 < CK / 4; r4++) {
        float4 sv[2];
        #pragma unroll
        for (int j = 0; j < 2; j++)
            sv[j] = *(const float4*)&smem_s[(size_t)(tp + 16 * j) * CKP + r4 * 4];
        #pragma unroll
        for (int i = 0; i < 8; i++) {
            const float4 wv = __ldg((const float4*)(weight + (size_t)(tf * 8 + i) * CK + r4 * 4));
            #pragma unroll
            for (int j = 0; j < 2; j++)
                acc2[i][j] += wv.x * sv[j].x + wv.y * sv[j].y
                            + wv.z * sv[j].z + wv.w * sv[j].w;
        }
    }

    #pragma unroll
    for (int i = 0; i < 8; i++) {
        const int f = tf * 8 + i;
        float* ob = out + (size_t)((b * COUT + f) * NLAT + t) * NLON;
        #pragma unroll
        for (int j = 0; j < 2; j++) {
            const int p = p0 + tp + 16 * j;
            if (p < NLON) ob[p] = acc2[i][j];
        }
    }
}

// ---------------------------------------------------------------------------
// Launch. Inputs: x, quad_weights, psi_vals, weight, bias, psi_seg, psi_lat,
// psi_lon. Output: float32 (B, COUT, NLAT, NLON).
// ---------------------------------------------------------------------------
extern "C" void kernel_launch(void* const* d_in, const int* in_sizes, int n_in,
                              void* d_out, int out_size) {
    const float* x      = (const float*)d_in[0];
    const float* qw     = (const float*)d_in[1];
    const float* vals   = (const float*)d_in[2];
    const float* weight = (const float*)d_in[3];
    const float* bias   = (const float*)d_in[4];
    const int*   seg    = (const int*)d_in[5];
    const int*   lat    = (const int*)d_in[6];
    const int*   lon    = (const int*)d_in[7];
    const int    nnz    = in_sizes[2];

    dim3 tgrid((CHW + 31) / 32, CIN / 32, BSZ);
    transpose_kernel<<<tgrid, dim3(32, 8)>>>(x);

    merge_kernel<<<(NLAT * 32 + 127) / 128, 128>>>(seg, lat, lon, vals, qw, nnz);

    const int smem_bytes = PT * CKP * sizeof(float) + CHUNK * sizeof(float4); // 53760
    cudaFuncSetAttribute(disco_kernel,
                         cudaFuncAttributeMaxDynamicSharedMemorySize, smem_bytes);
    dim3 grid(NPT, NLAT, BSZ);
    disco_kernel<<<grid, 256, smem_bytes>>>(weight, bias, (float*)d_out);
}

// round 4
// speedup vs baseline: 1.8483x; 1.1296x over previous
#include <cuda_runtime.h>

// Problem constants
#define NLAT 181
#define NLON 360
#define CIN  128
#define COUT 128
#define KS   3
#define BSZ  2
#define CHW  (NLAT * NLON)     // 65160
#define CK   (CIN * KS)        // 384
#define PT   32                // gather p-tile
#define NPT  12
#define TSLOT 2048
#define CHUNK 256
#define MTOT  (BSZ * CHW)      // 130320  (m = (b*181+t)*360+p)
#define MTILE 128
#define MBLK  ((MTOT + MTILE - 1) / MTILE)   // 1019
#define MPADL (MBLK * MTILE)                 // 130432
#define KC    48               // 384 / 8 k-chunks

// Scratch (device globals — allocation-free)
__device__ float  g_xt[(size_t)BSZ * CHW * CIN];   // x transposed: [b][h*w][c]
__device__ float4 g_rec[NLAT * TSLOT];             // {w0,w1,w2, bitcast((la<<9)|lo)}
__device__ int    g_tcnt[NLAT];
__device__ float  g_wt[CK * COUT];                 // W transposed: [ck][f]
__device__ float  g_z[(size_t)CK * MPADL];         // z K-major: [ck][m]

// f32x2 helpers
__device__ __forceinline__ void fma2(unsigned long long& d,
                                     unsigned long long a,
                                     unsigned long long b) {
    asm("fma.rn.f32x2 %0, %1, %2, %0;" : "+l"(d) : "l"(a), "l"(b));
}
__device__ __forceinline__ unsigned long long pack2(float x, float y) {
    unsigned long long r;
    asm("mov.b64 %0, {%1, %2};" : "=l"(r) : "f"(x), "f"(y));
    return r;
}
union F4U { float4 f; unsigned long long u[2]; };
union U2F { unsigned long long u; float2 f; };

// ---------------------------------------------------------------------------
// Transpose x[b][c][hw] -> g_xt[b][hw][c]
// ---------------------------------------------------------------------------
__global__ void transpose_kernel(const float* __restrict__ x) {
    __shared__ float tile[32][33];
    const int hw0 = blockIdx.x * 32;
    const int c0  = blockIdx.y * 32;
    const int b   = blockIdx.z;
    const int tx = threadIdx.x, ty = threadIdx.y;   // 32 x 8
    #pragma unroll
    for (int i = 0; i < 4; i++) {
        int c  = c0 + ty + i * 8;
        int hw = hw0 + tx;
        if (hw < CHW)
            tile[ty + i * 8][tx] = x[((size_t)b * CIN + c) * CHW + hw];
    }
    __syncthreads();
    #pragma unroll
    for (int i = 0; i < 4; i++) {
        int hw = hw0 + ty + i * 8;
        int c  = c0 + tx;
        if (hw < CHW)
            g_xt[((size_t)b * CHW + hw) * CIN + c] = tile[tx][ty + i * 8];
    }
}

// W[f][ck] -> g_wt[ck][f]
__global__ void wt_kernel(const float* __restrict__ w) {
    int i = blockIdx.x * 256 + threadIdx.x;
    if (i < CK * COUT) {
        int k = i / COUT, f = i % COUT;
        g_wt[i] = w[f * CK + k];
    }
}

// ---------------------------------------------------------------------------
// Merge: one warp per t; emit branch-free records {w0,w1,w2,pos}.
// ---------------------------------------------------------------------------
__global__ void merge_kernel(const int* __restrict__ seg,
                             const int* __restrict__ lat,
                             const int* __restrict__ lon,
                             const float* __restrict__ vals,
                             const float* __restrict__ qw,
                             int nnz) {
    const int t    = (blockIdx.x * blockDim.x + threadIdx.x) >> 5;
    const int lane = threadIdx.x & 31;
    if (t >= NLAT) return;

    int sb[4];
    #pragma unroll
    for (int k = 0; k < 4; k++) {
        const int j = t * KS + k;
        int lo = 0, hi = nnz;
        while (lo < hi) {
            int m = (lo + hi) >> 1;
            int sgv = seg[m];
            int key = (sgv % NLAT) * KS + (sgv / NLAT);
            if (key < j) lo = m + 1; else hi = m;
        }
        sb[k] = lo;
    }

    int mycnt = 0, base = 0;
    for (int pass = 0; pass < 2; pass++) {
        int widx = 0;
        for (int la = lane; la < NLAT; la += 32) {
            int bks[3], eks[3];
            #pragma unroll
            for (int k = 0; k < 3; k++) {
                int lo = sb[k], hi = sb[k + 1];
                while (lo < hi) { int m = (lo + hi) >> 1; if (lat[m] < la) lo = m + 1; else hi = m; }
                bks[k] = lo;
                hi = sb[k + 1];
                while (lo < hi) { int m = (lo + hi) >> 1; if (lat[m] < la + 1) lo = m + 1; else hi = m; }
                eks[k] = lo;
            }
            int p0 = bks[0], p1 = bks[1], p2 = bks[2];
            const float q = qw[la];
            while (p0 < eks[0] || p1 < eks[1] || p2 < eks[2]) {
                int l0 = (p0 < eks[0]) ? lon[p0] : 0x7fffffff;
                int l1 = (p1 < eks[1]) ? lon[p1] : 0x7fffffff;
                int l2 = (p2 < eks[2]) ? lon[p2] : 0x7fffffff;
                int lm = min(l0, min(l1, l2));
                float w0 = 0.f, w1 = 0.f, w2 = 0.f;
                if (l0 == lm) { w0 = vals[p0] * q; p0++; }
                if (l1 == lm) { w1 = vals[p1] * q; p1++; }
                if (l2 == lm) { w2 = vals[p2] * q; p2++; }
                if (w0 == 0.f && w1 == 0.f && w2 == 0.f) continue;
                if (pass == 1) {
                    int idx = base + widx;
                    if (idx < TSLOT)
                        g_rec[t * TSLOT + idx] =
                            make_float4(w0, w1, w2, __int_as_float((la << 9) | lm));
                }
                widx++;
            }
        }
        if (pass == 0) {
            mycnt = widx;
            int off = mycnt;
            #pragma unroll
            for (int d = 1; d < 32; d <<= 1) {
                int v = __shfl_up_sync(0xffffffffu, off, d);
                if (lane >= d) off += v;
            }
            base = off - mycnt;
            if (lane == 31) g_tcnt[t] = min(off, TSLOT);
        }
    }
}

// ---------------------------------------------------------------------------
// Stage 1: gather. Block = (p-tile 32, t, b). Per entry: 4x LDG.128 + 24 FFMA2.
// Writes z in K-major layout: g_z[ck][m], STG.128 over 4 contiguous p.
// ---------------------------------------------------------------------------
__global__ void __launch_bounds__(256, 2)
gather_kernel() {
    __shared__ float4 s_ent[CHUNK];

    const int tid  = threadIdx.x;
    const int warp = tid >> 5;
    const int lane = tid & 31;

    const int yb = blockIdx.y;
    const int t  = (yb & 1) ? (NLAT - 1 - (yb >> 1)) : (yb >> 1);   // pole-first
    const int b  = blockIdx.z;
    const int p0 = blockIdx.x * PT;
    const int pbase = p0 + warp * 4;

    const int tcnt = g_tcnt[t];
    const float4* rec = g_rec + (size_t)t * TSLOT;
    const float4* xb  = (const float4*)(g_xt + (size_t)b * CHW * CIN);

    unsigned long long a2[3][4][2];
    #pragma unroll
    for (int k = 0; k < 3; k++)
        #pragma unroll
        for (int q = 0; q < 4; q++) { a2[k][q][0] = 0ull; a2[k][q][1] = 0ull; }

    for (int c0 = 0; c0 < tcnt; c0 += CHUNK) {
        const int n = min(CHUNK, tcnt - c0);
        __syncthreads();
        for (int i = tid; i < n; i += 256) s_ent[i] = __ldg(&rec[c0 + i]);
        __syncthreads();

        #pragma unroll 2
        for (int e = 0; e < n; e++) {
            const float4 r = s_ent[e];
            const int pos = __float_as_int(r.w);
            const int lo  = pos & 511;
            const int la  = pos >> 9;
            const unsigned long long w0 = pack2(r.x, r.x);
            const unsigned long long w1 = pack2(r.y, r.y);
            const unsigned long long w2 = pack2(r.z, r.z);
            const int rowb = la * NLON;
            #pragma unroll
            for (int q = 0; q < 4; q++) {
                int lp = lo + pbase + q;
                if (lp >= NLON) lp -= NLON;
                if (lp >= NLON) lp -= NLON;
                F4U xv;
                xv.f = xb[(size_t)(rowb + lp) * 32 + lane];
                fma2(a2[0][q][0], w0, xv.u[0]);
                fma2(a2[0][q][1], w0, xv.u[1]);
                fma2(a2[1][q][0], w1, xv.u[0]);
                fma2(a2[1][q][1], w1, xv.u[1]);
                fma2(a2[2][q][0], w2, xv.u[0]);
                fma2(a2[2][q][1], w2, xv.u[1]);
            }
        }
    }

    // store to z[ck][m]: ck = (4*lane+j)*3 + k, m = (b*181+t)*360 + pbase + q
    if (pbase < NLON) {
        const size_t mb = (size_t)(b * NLAT + t) * NLON + pbase;
        #pragma unroll
        for (int j = 0; j < 4; j++) {
            const int h = j >> 1;
            #pragma unroll
            for (int k = 0; k < 3; k++) {
                U2F t0, t1, t2, t3;
                t0.u = a2[k][0][h]; t1.u = a2[k][1][h];
                t2.u = a2[k][2][h]; t3.u = a2[k][3][h];
                float4 v = (j & 1)
                    ? make_float4(t0.f.y, t1.f.y, t2.f.y, t3.f.y)
                    : make_float4(t0.f.x, t1.f.x, t2.f.x, t3.f.x);
                *(float4*)&g_z[(size_t)(lane * 12 + j * 3 + k) * MPADL + mb] = v;
            }
        }
    }
}

// ---------------------------------------------------------------------------
// Stage 2: GEMM. out[m][f] = sum_ck z[ck][m] * wt[ck][f] + bias[f].
// Block: 128m x 128f, K in double-buffered 8-row smem chunks.
// Thread: 8m x 8f, f32x2 packed over m-pairs.
// ---------------------------------------------------------------------------
__global__ void __launch_bounds__(256, 2)
gemm_kernel(const float* __restrict__ bias, float* __restrict__ out) {
    __shared__ float sA[2][8][MTILE];
    __shared__ float sB[2][8][COUT];

    const int tid = threadIdx.x;
    const int m0  = blockIdx.x * MTILE;
    const int mt  = tid & 15;       // m-group: m0 + mt*4 (+64)
    const int ft  = tid >> 4;       // f-group: ft*8
    const int lr  = tid >> 5;       // load row 0..7
    const int lc  = (tid & 31) * 4; // load col

    unsigned long long acc[4][8];
    #pragma unroll
    for (int i = 0; i < 8; i++) {
        const float bv = __ldg(bias + ft * 8 + i);
        const unsigned long long bp = pack2(bv, bv);
        #pragma unroll
        for (int p = 0; p < 4; p++) acc[p][i] = bp;
    }

    float4 pa = *(const float4*)&g_z[(size_t)lr * MPADL + m0 + lc];
    float4 pb = __ldg((const float4*)&g_wt[lr * COUT + lc]);
    *(float4*)&sA[0][lr][lc] = pa;
    *(float4*)&sB[0][lr][lc] = pb;
    __syncthreads();

    int buf = 0;
    for (int kc = 0; kc < KC; kc++) {
        if (kc + 1 < KC) {
            pa = *(const float4*)&g_z[(size_t)((kc + 1) * 8 + lr) * MPADL + m0 + lc];
            pb = __ldg((const float4*)&g_wt[((kc + 1) * 8 + lr) * COUT + lc]);
        }
        #pragma unroll
        for (int k = 0; k < 8; k++) {
            F4U a0, a1;
            a0.f = *(const float4*)&sA[buf][k][mt * 4];
            a1.f = *(const float4*)&sA[buf][k][64 + mt * 4];
            const float4 b0 = *(const float4*)&sB[buf][k][ft * 8];
            const float4 b1 = *(const float4*)&sB[buf][k][ft * 8 + 4];
            unsigned long long w[8];
            w[0] = pack2(b0.x, b0.x); w[1] = pack2(b0.y, b0.y);
            w[2] = pack2(b0.z, b0.z); w[3] = pack2(b0.w, b0.w);
            w[4] = pack2(b1.x, b1.x); w[5] = pack2(b1.y, b1.y);
            w[6] = pack2(b1.z, b1.z); w[7] = pack2(b1.w, b1.w);
            #pragma unroll
            for (int i = 0; i < 8; i++) {
                fma2(acc[0][i], a0.u[0], w[i]);
                fma2(acc[1][i], a0.u[1], w[i]);
                fma2(acc[2][i], a1.u[0], w[i]);
                fma2(acc[3][i], a1.u[1], w[i]);
            }
        }
        if (kc + 1 < KC) {
            buf ^= 1;
            *(float4*)&sA[buf][lr][lc] = pa;
            *(float4*)&sB[buf][lr][lc] = pb;
            __syncthreads();
        }
    }

    // Epilogue: out index = b*COUT*CHW + f*CHW + (m % CHW), b = m / CHW.
    #pragma unroll
    for (int half = 0; half < 2; half++) {
        const int mq = m0 + half * 64 + mt * 4;   // 4-aligned quad
        if (mq >= MTOT) continue;
        const int bq  = mq / CHW;
        const int rem = mq - bq * CHW;
        float* obase = out + (size_t)bq * COUT * CHW + rem;
        #pragma unroll
        for (int i = 0; i < 8; i++) {
            const int f = ft * 8 + i;
            U2F lo, hi;
            lo.u = acc[2 * half][i];
            hi.u = acc[2 * half + 1][i];
            float4 v = make_float4(lo.f.x, lo.f.y, hi.f.x, hi.f.y);
            *(float4*)&obase[(size_t)f * CHW] = v;
        }
    }
}

// ---------------------------------------------------------------------------
// Launch. Inputs: x, quad_weights, psi_vals, weight, bias, psi_seg, psi_lat,
// psi_lon. Output: float32 (B, COUT, NLAT, NLON).
// ---------------------------------------------------------------------------
extern "C" void kernel_launch(void* const* d_in, const int* in_sizes, int n_in,
                              void* d_out, int out_size) {
    const float* x      = (const float*)d_in[0];
    const float* qw     = (const float*)d_in[1];
    const float* vals   = (const float*)d_in[2];
    const float* weight = (const float*)d_in[3];
    const float* bias   = (const float*)d_in[4];
    const int*   seg    = (const int*)d_in[5];
    const int*   lat    = (const int*)d_in[6];
    const int*   lon    = (const int*)d_in[7];
    const int    nnz    = in_sizes[2];

    dim3 tgrid((CHW + 31) / 32, CIN / 32, BSZ);
    transpose_kernel<<<tgrid, dim3(32, 8)>>>(x);
    wt_kernel<<<(CK * COUT + 255) / 256, 256>>>(weight);
    merge_kernel<<<(NLAT * 32 + 127) / 128, 128>>>(seg, lat, lon, vals, qw, nnz);

    dim3 ggrid(NPT, NLAT, BSZ);
    gather_kernel<<<ggrid, 256>>>();

    gemm_kernel<<<MBLK, 256>>>(bias, (float*)d_out);
}

// round 5
// speedup vs baseline: 1.8828x; 1.0187x over previous
#include <cuda_runtime.h>

// Problem constants
#define NLAT 181
#define NLON 360
#define CIN  128
#define COUT 128
#define KS   3
#define BSZ  2
#define CHW  (NLAT * NLON)     // 65160
#define CK   (CIN * KS)        // 384
#define PT   32                // gather p-tile
#define NPT  12
#define MTOT  (BSZ * CHW)      // 130320
#define MTILE 128
#define MBLK  ((MTOT + MTILE - 1) / MTILE)   // 1019
#define MPADL (MBLK * MTILE)                 // 130432
#define KC    48               // 384 / 8
#define WSLOT 4096             // padded weight entries per t
#define RSLOT 512              // runs per t

// Scratch (device globals — allocation-free)
__device__ float  g_xt[(size_t)BSZ * CHW * CIN];   // x transposed: [b][h*w][c]
__device__ float4 g_rw[NLAT * WSLOT];              // run weights {w0,w1,w2,0}, zero-padded
__device__ int4   g_runs[NLAT * RSLOT];            // {la, lo0, cnt_padded, wabs}
__device__ int    g_rcnt[NLAT];
__device__ float  g_wt[CK * COUT];                 // W transposed: [ck][f]
__device__ float  g_z[(size_t)CK * MPADL];         // z K-major: [ck][m]

// f32x2 helpers
__device__ __forceinline__ void fma2(unsigned long long& d,
                                     unsigned long long a,
                                     unsigned long long b) {
    asm("fma.rn.f32x2 %0, %1, %2, %0;" : "+l"(d) : "l"(a), "l"(b));
}
__device__ __forceinline__ unsigned long long pack2(float x, float y) {
    unsigned long long r;
    asm("mov.b64 %0, {%1, %2};" : "=l"(r) : "f"(x), "f"(y));
    return r;
}
union F4U { float4 f; unsigned long long u[2]; };
union U2F { unsigned long long u; float2 f; };

// ---------------------------------------------------------------------------
// Transpose x[b][c][hw] -> g_xt[b][hw][c]
// ---------------------------------------------------------------------------
__global__ void transpose_kernel(const float* __restrict__ x) {
    __shared__ float tile[32][33];
    const int hw0 = blockIdx.x * 32;
    const int c0  = blockIdx.y * 32;
    const int b   = blockIdx.z;
    const int tx = threadIdx.x, ty = threadIdx.y;
    #pragma unroll
    for (int i = 0; i < 4; i++) {
        int c  = c0 + ty + i * 8;
        int hw = hw0 + tx;
        if (hw < CHW)
            tile[ty + i * 8][tx] = x[((size_t)b * CIN + c) * CHW + hw];
    }
    __syncthreads();
    #pragma unroll
    for (int i = 0; i < 4; i++) {
        int hw = hw0 + ty + i * 8;
        int c  = c0 + tx;
        if (hw < CHW)
            g_xt[((size_t)b * CHW + hw) * CIN + c] = tile[tx][ty + i * 8];
    }
}

// W[f][ck] -> g_wt[ck][f]
__global__ void wt_kernel(const float* __restrict__ w) {
    int i = blockIdx.x * 256 + threadIdx.x;
    if (i < CK * COUT) {
        int k = i / COUT, f = i % COUT;
        g_wt[i] = w[f * CK + k];
    }
}

// ---------------------------------------------------------------------------
// Merge: warp per t. Emits per-(t,la) runs of consecutive lons with
// branch-free weight triples, zero-padded to multiples of 4 entries.
// ---------------------------------------------------------------------------
__global__ void merge_kernel(const int* __restrict__ seg,
                             const int* __restrict__ lat,
                             const int* __restrict__ lon,
                             const float* __restrict__ vals,
                             const float* __restrict__ qw,
                             int nnz) {
    const int t    = (blockIdx.x * blockDim.x + threadIdx.x) >> 5;
    const int lane = threadIdx.x & 31;
    if (t >= NLAT) return;

    int sb[4];
    #pragma unroll
    for (int k = 0; k < 4; k++) {
        const int j = t * KS + k;
        int lo = 0, hi = nnz;
        while (lo < hi) {
            int m = (lo + hi) >> 1;
            int sgv = seg[m];
            int key = (sgv % NLAT) * KS + (sgv / NLAT);
            if (key < j) lo = m + 1; else hi = m;
        }
        sb[k] = lo;
    }

    const int wlim = (t + 1) * WSLOT;
    int wabs = 0, rbase = 0;   // set after pass 0
    int entc = 0, runsc = 0;

    for (int pass = 0; pass < 2; pass++) {
        int ent = 0, runs = 0;
        for (int la = lane; la < NLAT; la += 32) {
            int bks[3], eks[3];
            #pragma unroll
            for (int k = 0; k < 3; k++) {
                int lo = sb[k], hi = sb[k + 1];
                while (lo < hi) { int m = (lo + hi) >> 1; if (lat[m] < la) lo = m + 1; else hi = m; }
                bks[k] = lo;
                hi = sb[k + 1];
                while (lo < hi) { int m = (lo + hi) >> 1; if (lat[m] < la + 1) lo = m + 1; else hi = m; }
                eks[k] = lo;
            }
            int p0 = bks[0], p1 = bks[1], p2 = bks[2];
            const float q = qw[la];
            int prev = -2, rstart = ent, rcnt = 0, rlo0 = 0;
            while (p0 < eks[0] || p1 < eks[1] || p2 < eks[2]) {
                int l0 = (p0 < eks[0]) ? lon[p0] : 0x7fffffff;
                int l1 = (p1 < eks[1]) ? lon[p1] : 0x7fffffff;
                int l2 = (p2 < eks[2]) ? lon[p2] : 0x7fffffff;
                int lm = min(l0, min(l1, l2));
                float w0 = 0.f, w1 = 0.f, w2 = 0.f;
                if (l0 == lm) { w0 = vals[p0] * q; p0++; }
                if (l1 == lm) { w1 = vals[p1] * q; p1++; }
                if (l2 == lm) { w2 = vals[p2] * q; p2++; }
                if (w0 == 0.f && w1 == 0.f && w2 == 0.f) continue;
                if (rcnt > 0 && lm != prev + 1) {
                    // close current run
                    int pad = (4 - (rcnt & 3)) & 3;
                    if (pass == 1) {
                        for (int z = 0; z < pad; z++) {
                            int ai = wabs + rstart + rcnt + z;
                            if (ai < wlim) g_rw[ai] = make_float4(0.f, 0.f, 0.f, 0.f);
                        }
                        int ri = rbase + runs;
                        if (ri < RSLOT)
                            g_runs[t * RSLOT + ri] =
                                make_int4(la, rlo0, rcnt + pad, wabs + rstart);
                    }
                    runs++;
                    ent = rstart + rcnt + pad;
                    rstart = ent; rcnt = 0;
                }
                if (rcnt == 0) rlo0 = lm;
                if (pass == 1) {
                    int ai = wabs + rstart + rcnt;
                    if (ai < wlim) g_rw[ai] = make_float4(w0, w1, w2, 0.f);
                }
                rcnt++;
                ent = rstart + rcnt;
                prev = lm;
            }
            if (rcnt > 0) {   // close trailing run of this la
                int pad = (4 - (rcnt & 3)) & 3;
                if (pass == 1) {
                    for (int z = 0; z < pad; z++) {
                        int ai = wabs + rstart + rcnt + z;
                        if (ai < wlim) g_rw[ai] = make_float4(0.f, 0.f, 0.f, 0.f);
                    }
                    int ri = rbase + runs;
                    if (ri < RSLOT)
                        g_runs[t * RSLOT + ri] =
                            make_int4(la, rlo0, rcnt + pad, wabs + rstart);
                }
                runs++;
                ent = rstart + rcnt + pad;
            }
        }
        if (pass == 0) {
            entc = ent; runsc = runs;
            int ei = entc, ri = runsc;
            #pragma unroll
            for (int d = 1; d < 32; d <<= 1) {
                int v = __shfl_up_sync(0xffffffffu, ei, d);
                int u = __shfl_up_sync(0xffffffffu, ri, d);
                if (lane >= d) { ei += v; ri += u; }
            }
            wabs  = t * WSLOT + (ei - entc);
            rbase = ri - runsc;
            if (lane == 31) g_rcnt[t] = min(ri, RSLOT);
        }
    }
}

// ---------------------------------------------------------------------------
// Stage 1: gather with rolling column window. Block = (p-tile 32, t, b).
// Per 4 entries: 4 batch LDG.128 + 4 uniform weight loads + 96 fma2.
// ---------------------------------------------------------------------------
__global__ void __launch_bounds__(256, 2)
gather_kernel() {
    const int tid  = threadIdx.x;
    const int warp = tid >> 5;
    const int lane = tid & 31;

    const int yb = blockIdx.y;
    const int t  = (yb & 1) ? (NLAT - 1 - (yb >> 1)) : (yb >> 1);   // pole-first
    const int b  = blockIdx.z;
    const int p0 = blockIdx.x * PT;
    const int pbase = p0 + warp * 4;

    const int nruns = g_rcnt[t];
    const int4* runs = g_runs + (size_t)t * RSLOT;
    const float4* xb = (const float4*)(g_xt + (size_t)b * CHW * CIN);

    unsigned long long a2[3][4][2];
    #pragma unroll
    for (int k = 0; k < 3; k++)
        #pragma unroll
        for (int q = 0; q < 4; q++) { a2[k][q][0] = 0ull; a2[k][q][1] = 0ull; }

    for (int r = 0; r < nruns; r++) {
        const int4 rn = __ldg(&runs[r]);
        const int la   = rn.x;
        const int cnt  = rn.z;                 // multiple of 4
        const float4* wp = g_rw + rn.w;
        const int rowb = la * NLON;

        int col = rn.y + pbase;                // first column (entry 0, q=0)
        if (col >= NLON) col -= NLON;
        if (col >= NLON) col -= NLON;
        int c1 = col + 1; if (c1 >= NLON) c1 -= NLON;
        int c2 = c1 + 1;  if (c2 >= NLON) c2 -= NLON;

        F4U w0v, w1v, w2v;                     // window: cols j, j+1, j+2
        w0v.f = xb[(size_t)(rowb + col) * 32 + lane];
        w1v.f = xb[(size_t)(rowb + c1)  * 32 + lane];
        w2v.f = xb[(size_t)(rowb + c2)  * 32 + lane];
        int colx = c2;                          // last loaded column

        for (int j4 = 0; j4 < cnt; j4 += 4) {
            // batch-load the next 4 columns (j4+3 .. j4+6)
            int n0 = colx + 1; if (n0 >= NLON) n0 -= NLON;
            int n1 = n0 + 1;   if (n1 >= NLON) n1 -= NLON;
            int n2 = n1 + 1;   if (n2 >= NLON) n2 -= NLON;
            int n3 = n2 + 1;   if (n3 >= NLON) n3 -= NLON;
            colx = n3;
            F4U nw0, nw1, nw2, nw3;
            nw0.f = xb[(size_t)(rowb + n0) * 32 + lane];
            nw1.f = xb[(size_t)(rowb + n1) * 32 + lane];
            nw2.f = xb[(size_t)(rowb + n2) * 32 + lane];
            nw3.f = xb[(size_t)(rowb + n3) * 32 + lane];

            float4 wa = __ldg(&wp[j4 + 0]);
            float4 wb = __ldg(&wp[j4 + 1]);
            float4 wc = __ldg(&wp[j4 + 2]);
            float4 wd = __ldg(&wp[j4 + 3]);

            // entry u uses columns j4+u .. j4+u+3
            #define DO_ENTRY(W, V0, V1, V2, V3)                                   \
            {                                                                     \
                unsigned long long k0 = pack2(W.x, W.x);                          \
                unsigned long long k1 = pack2(W.y, W.y);                          \
                unsigned long long k2 = pack2(W.z, W.z);                          \
                fma2(a2[0][0][0], k0, V0.u[0]); fma2(a2[0][0][1], k0, V0.u[1]);   \
                fma2(a2[1][0][0], k1, V0.u[0]); fma2(a2[1][0][1], k1, V0.u[1]);   \
                fma2(a2[2][0][0], k2, V0.u[0]); fma2(a2[2][0][1], k2, V0.u[1]);   \
                fma2(a2[0][1][0], k0, V1.u[0]); fma2(a2[0][1][1], k0, V1.u[1]);   \
                fma2(a2[1][1][0], k1, V1.u[0]); fma2(a2[1][1][1], k1, V1.u[1]);   \
                fma2(a2[2][1][0], k2, V1.u[0]); fma2(a2[2][1][1], k2, V1.u[1]);   \
                fma2(a2[0][2][0], k0, V2.u[0]); fma2(a2[0][2][1], k0, V2.u[1]);   \
                fma2(a2[1][2][0], k1, V2.u[0]); fma2(a2[1][2][1], k1, V2.u[1]);   \
                fma2(a2[2][2][0], k2, V2.u[0]); fma2(a2[2][2][1], k2, V2.u[1]);   \
                fma2(a2[0][3][0], k0, V3.u[0]); fma2(a2[0][3][1], k0, V3.u[1]);   \
                fma2(a2[1][3][0], k1, V3.u[0]); fma2(a2[1][3][1], k1, V3.u[1]);   \
                fma2(a2[2][3][0], k2, V3.u[0]); fma2(a2[2][3][1], k2, V3.u[1]);   \
            }
            DO_ENTRY(wa, w0v, w1v, w2v, nw0)
            DO_ENTRY(wb, w1v, w2v, nw0, nw1)
            DO_ENTRY(wc, w2v, nw0, nw1, nw2)
            DO_ENTRY(wd, nw0, nw1, nw2, nw3)
            #undef DO_ENTRY
            w0v = nw1; w1v = nw2; w2v = nw3;
        }
    }

    // store to z[ck][m]: ck = (4*lane+j)*3 + k, m = (b*181+t)*360 + pbase + q
    if (pbase < NLON) {
        const size_t mb = (size_t)(b * NLAT + t) * NLON + pbase;
        #pragma unroll
        for (int j = 0; j < 4; j++) {
            const int h = j >> 1;
            #pragma unroll
            for (int k = 0; k < 3; k++) {
                U2F t0, t1, t2, t3;
                t0.u = a2[k][0][h]; t1.u = a2[k][1][h];
                t2.u = a2[k][2][h]; t3.u = a2[k][3][h];
                float4 v = (j & 1)
                    ? make_float4(t0.f.y, t1.f.y, t2.f.y, t3.f.y)
                    : make_float4(t0.f.x, t1.f.x, t2.f.x, t3.f.x);
                *(float4*)&g_z[(size_t)(lane * 12 + j * 3 + k) * MPADL + mb] = v;
            }
        }
    }
}

// ---------------------------------------------------------------------------
// Stage 2: GEMM. out[m][f] = sum_ck z[ck][m] * wt[ck][f] + bias[f].
// B staged pre-duplicated (b,b) pairs -> LDS.64 operands, no packing movs.
// ---------------------------------------------------------------------------
__global__ void __launch_bounds__(256, 2)
gemm_kernel(const float* __restrict__ bias, float* __restrict__ out) {
    __shared__ float sA[2][8][MTILE];
    __shared__ float sB2[2][8][2 * COUT];

    const int tid = threadIdx.x;
    const int m0  = blockIdx.x * MTILE;
    const int mt  = tid & 15;
    const int ft  = tid >> 4;
    const int lr  = tid >> 5;
    const int lc  = (tid & 31) * 4;

    unsigned long long acc[4][8];
    #pragma unroll
    for (int i = 0; i < 8; i++) {
        const float bv = __ldg(bias + ft * 8 + i);
        const unsigned long long bp = pack2(bv, bv);
        #pragma unroll
        for (int p = 0; p < 4; p++) acc[p][i] = bp;
    }

    float4 pa = *(const float4*)&g_z[(size_t)lr * MPADL + m0 + lc];
    float4 pb = __ldg((const float4*)&g_wt[lr * COUT + lc]);
    *(float4*)&sA[0][lr][lc] = pa;
    *(float4*)&sB2[0][lr][2 * lc]     = make_float4(pb.x, pb.x, pb.y, pb.y);
    *(float4*)&sB2[0][lr][2 * lc + 4] = make_float4(pb.z, pb.z, pb.w, pb.w);
    __syncthreads();

    int buf = 0;
    for (int kc = 0; kc < KC; kc++) {
        if (kc + 1 < KC) {
            pa = *(const float4*)&g_z[(size_t)((kc + 1) * 8 + lr) * MPADL + m0 + lc];
            pb = __ldg((const float4*)&g_wt[((kc + 1) * 8 + lr) * COUT + lc]);
        }
        #pragma unroll
        for (int k = 0; k < 8; k++) {
            F4U a0, a1;
            a0.f = *(const float4*)&sA[buf][k][mt * 4];
            a1.f = *(const float4*)&sA[buf][k][64 + mt * 4];
            unsigned long long w[8];
            #pragma unroll
            for (int i = 0; i < 8; i++)
                w[i] = *(const unsigned long long*)&sB2[buf][k][(ft * 8 + i) * 2];
            #pragma unroll
            for (int i = 0; i < 8; i++) {
                fma2(acc[0][i], a0.u[0], w[i]);
                fma2(acc[1][i], a0.u[1], w[i]);
                fma2(acc[2][i], a1.u[0], w[i]);
                fma2(acc[3][i], a1.u[1], w[i]);
            }
        }
        if (kc + 1 < KC) {
            buf ^= 1;
            *(float4*)&sA[buf][lr][lc] = pa;
            *(float4*)&sB2[buf][lr][2 * lc]     = make_float4(pb.x, pb.x, pb.y, pb.y);
            *(float4*)&sB2[buf][lr][2 * lc + 4] = make_float4(pb.z, pb.z, pb.w, pb.w);
            __syncthreads();
        }
    }

    #pragma unroll
    for (int half = 0; half < 2; half++) {
        const int mq = m0 + half * 64 + mt * 4;
        if (mq >= MTOT) continue;
        const int bq  = mq / CHW;
        const int rem = mq - bq * CHW;
        float* obase = out + (size_t)bq * COUT * CHW + rem;
        #pragma unroll
        for (int i = 0; i < 8; i++) {
            const int f = ft * 8 + i;
            U2F lo, hi;
            lo.u = acc[2 * half][i];
            hi.u = acc[2 * half + 1][i];
            float4 v = make_float4(lo.f.x, lo.f.y, hi.f.x, hi.f.y);
            *(float4*)&obase[(size_t)f * CHW] = v;
        }
    }
}

// ---------------------------------------------------------------------------
// Launch.
// ---------------------------------------------------------------------------
extern "C" void kernel_launch(void* const* d_in, const int* in_sizes, int n_in,
                              void* d_out, int out_size) {
    const float* x      = (const float*)d_in[0];
    const float* qw     = (const float*)d_in[1];
    const float* vals   = (const float*)d_in[2];
    const float* weight = (const float*)d_in[3];
    const float* bias   = (const float*)d_in[4];
    const int*   seg    = (const int*)d_in[5];
    const int*   lat    = (const int*)d_in[6];
    const int*   lon    = (const int*)d_in[7];
    const int    nnz    = in_sizes[2];

    dim3 tgrid((CHW + 31) / 32, CIN / 32, BSZ);
    transpose_kernel<<<tgrid, dim3(32, 8)>>>(x);
    wt_kernel<<<(CK * COUT + 255) / 256, 256>>>(weight);
    merge_kernel<<<(NLAT * 32 + 127) / 128, 128>>>(seg, lat, lon, vals, qw, nnz);

    dim3 ggrid(NPT, NLAT, BSZ);
    gather_kernel<<<ggrid, 256>>>();

    gemm_kernel<<<MBLK, 256>>>(bias, (float*)d_out);
}

// round 7
// speedup vs baseline: 2.5408x; 1.3494x over previous
#include <cuda_runtime.h>
#include <cstdint>

// Problem constants
#define NLAT 181
#define NLON 360
#define CIN  128
#define COUT 128
#define KS   3
#define BSZ  2
#define CHW  (NLAT * NLON)     // 65160
#define CK   (CIN * KS)        // 384
#define PT   32                // gather p-tile
#define NPT  12
#define MTOT  (BSZ * CHW)      // 130320
#define MTILE 128
#define MBLK  ((MTOT + MTILE - 1) / MTILE)   // 1019
#define MPADL (MBLK * MTILE)                 // 130432
#define WSLOT 4096
#define RSLOT 512
#define KCH   32               // GEMM K-chunk
#define NCH   (CK / KCH)       // 12
#define SROW  36               // padded smem row (words): bank = 4g+tg, conflict-free

// Scratch (device globals — allocation-free; zero-init so padded z rows are 0)
__device__ float  g_xt[(size_t)BSZ * CHW * CIN];   // x transposed: [b][h*w][c]
__device__ float4 g_rw[NLAT * WSLOT];              // run weights {w0,w1,w2,0}
__device__ int4   g_runs[NLAT * RSLOT];            // {la, lo0, cnt_padded, wabs}
__device__ int    g_rcnt[NLAT];
__device__ float  g_z[(size_t)MPADL * CK];         // z M-major [m][ck], tf32-rounded
__device__ float  g_wtf[COUT * CK];                // W [f][ck], tf32-rounded

// ---------------- helpers ----------------
__device__ __forceinline__ void fma2(unsigned long long& d,
                                     unsigned long long a,
                                     unsigned long long b) {
    asm("fma.rn.f32x2 %0, %1, %2, %0;" : "+l"(d) : "l"(a), "l"(b));
}
__device__ __forceinline__ unsigned long long pack2(float x, float y) {
    unsigned long long r;
    asm("mov.b64 %0, {%1, %2};" : "=l"(r) : "f"(x), "f"(y));
    return r;
}
union F4U { float4 f; unsigned long long u[2]; };
union U2F { unsigned long long u; float2 f; };

__device__ __forceinline__ float tf32r(float x) {
    uint32_t r;
    asm("cvt.rn.tf32.f32 %0, %1;" : "=r"(r) : "f"(x));
    return __uint_as_float(r);
}
__device__ __forceinline__ uint32_t smem_u32(const void* p) {
    uint32_t a;
    asm("{ .reg .u64 t; cvta.to.shared.u64 t, %1; cvt.u32.u64 %0, t; }"
        : "=r"(a) : "l"(p));
    return a;
}
__device__ __forceinline__ void cpasync16(uint32_t s, const void* g) {
    asm volatile("cp.async.cg.shared.global [%0], [%1], 16;" :: "r"(s), "l"(g));
}
__device__ __forceinline__ void cp_commit() {
    asm volatile("cp.async.commit_group;" ::: "memory");
}
template <int N>
__device__ __forceinline__ void cp_wait() {
    asm volatile("cp.async.wait_group %0;" :: "n"(N) : "memory");
}
__device__ __forceinline__ void mma_tf32(float* d, const uint32_t* a,
                                         uint32_t b0, uint32_t b1) {
    asm volatile(
        "mma.sync.aligned.m16n8k8.row.col.f32.tf32.tf32.f32 "
        "{%0,%1,%2,%3}, {%4,%5,%6,%7}, {%8,%9}, {%0,%1,%2,%3};"
        : "+f"(d[0]), "+f"(d[1]), "+f"(d[2]), "+f"(d[3])
        : "r"(a[0]), "r"(a[1]), "r"(a[2]), "r"(a[3]), "r"(b0), "r"(b1));
}

// ---------------------------------------------------------------------------
// Transpose x[b][c][hw] -> g_xt[b][hw][c]
// ---------------------------------------------------------------------------
__global__ void transpose_kernel(const float* __restrict__ x) {
    __shared__ float tile[32][33];
    const int hw0 = blockIdx.x * 32;
    const int c0  = blockIdx.y * 32;
    const int b   = blockIdx.z;
    const int tx = threadIdx.x, ty = threadIdx.y;
    #pragma unroll
    for (int i = 0; i < 4; i++) {
        int c  = c0 + ty + i * 8;
        int hw = hw0 + tx;
        if (hw < CHW)
            tile[ty + i * 8][tx] = x[((size_t)b * CIN + c) * CHW + hw];
    }
    __syncthreads();
    #pragma unroll
    for (int i = 0; i < 4; i++) {
        int hw = hw0 + ty + i * 8;
        int c  = c0 + tx;
        if (hw < CHW)
            g_xt[((size_t)b * CHW + hw) * CIN + c] = tile[tx][ty + i * 8];
    }
}

// W[f][ck] -> tf32-rounded copy
__global__ void wconv_kernel(const float* __restrict__ w) {
    int i = blockIdx.x * 256 + threadIdx.x;
    if (i < COUT * CK) g_wtf[i] = tf32r(w[i]);
}

// ---------------------------------------------------------------------------
// Merge: warp per t. Emits per-(t,la) runs of consecutive lons with
// branch-free weight triples, zero-padded to multiples of 4 entries.
// ---------------------------------------------------------------------------
__global__ void merge_kernel(const int* __restrict__ seg,
                             const int* __restrict__ lat,
                             const int* __restrict__ lon,
                             const float* __restrict__ vals,
                             const float* __restrict__ qw,
                             int nnz) {
    const int t    = (blockIdx.x * blockDim.x + threadIdx.x) >> 5;
    const int lane = threadIdx.x & 31;
    if (t >= NLAT) return;

    int sb[4];
    #pragma unroll
    for (int k = 0; k < 4; k++) {
        const int j = t * KS + k;
        int lo = 0, hi = nnz;
        while (lo < hi) {
            int m = (lo + hi) >> 1;
            int sgv = seg[m];
            int key = (sgv % NLAT) * KS + (sgv / NLAT);
            if (key < j) lo = m + 1; else hi = m;
        }
        sb[k] = lo;
    }

    const int wlim = (t + 1) * WSLOT;
    int wabs = 0, rbase = 0;
    int entc = 0, runsc = 0;

    for (int pass = 0; pass < 2; pass++) {
        int ent = 0, runs = 0;
        for (int la = lane; la < NLAT; la += 32) {
            int bks[3], eks[3];
            #pragma unroll
            for (int k = 0; k < 3; k++) {
                int lo = sb[k], hi = sb[k + 1];
                while (lo < hi) { int m = (lo + hi) >> 1; if (lat[m] < la) lo = m + 1; else hi = m; }
                bks[k] = lo;
                hi = sb[k + 1];
                while (lo < hi) { int m = (lo + hi) >> 1; if (lat[m] < la + 1) lo = m + 1; else hi = m; }
                eks[k] = lo;
            }
            int p0 = bks[0], p1 = bks[1], p2 = bks[2];
            const float q = qw[la];
            int prev = -2, rstart = ent, rcnt = 0, rlo0 = 0;
            while (p0 < eks[0] || p1 < eks[1] || p2 < eks[2]) {
                int l0 = (p0 < eks[0]) ? lon[p0] : 0x7fffffff;
                int l1 = (p1 < eks[1]) ? lon[p1] : 0x7fffffff;
                int l2 = (p2 < eks[2]) ? lon[p2] : 0x7fffffff;
                int lm = min(l0, min(l1, l2));
                float w0 = 0.f, w1 = 0.f, w2 = 0.f;
                if (l0 == lm) { w0 = vals[p0] * q; p0++; }
                if (l1 == lm) { w1 = vals[p1] * q; p1++; }
                if (l2 == lm) { w2 = vals[p2] * q; p2++; }
                if (w0 == 0.f && w1 == 0.f && w2 == 0.f) continue;
                if (rcnt > 0 && lm != prev + 1) {
                    int pad = (4 - (rcnt & 3)) & 3;
                    if (pass == 1) {
                        for (int z = 0; z < pad; z++) {
                            int ai = wabs + rstart + rcnt + z;
                            if (ai < wlim) g_rw[ai] = make_float4(0.f, 0.f, 0.f, 0.f);
                        }
                        int ri = rbase + runs;
                        if (ri < RSLOT)
                            g_runs[t * RSLOT + ri] =
                                make_int4(la, rlo0, rcnt + pad, wabs + rstart);
                    }
                    runs++;
                    ent = rstart + rcnt + pad;
                    rstart = ent; rcnt = 0;
                }
                if (rcnt == 0) rlo0 = lm;
                if (pass == 1) {
                    int ai = wabs + rstart + rcnt;
                    if (ai < wlim) g_rw[ai] = make_float4(w0, w1, w2, 0.f);
                }
                rcnt++;
                ent = rstart + rcnt;
                prev = lm;
            }
            if (rcnt > 0) {
                int pad = (4 - (rcnt & 3)) & 3;
                if (pass == 1) {
                    for (int z = 0; z < pad; z++) {
                        int ai = wabs + rstart + rcnt + z;
                        if (ai < wlim) g_rw[ai] = make_float4(0.f, 0.f, 0.f, 0.f);
                    }
                    int ri = rbase + runs;
                    if (ri < RSLOT)
                        g_runs[t * RSLOT + ri] =
                            make_int4(la, rlo0, rcnt + pad, wabs + rstart);
                }
                runs++;
                ent = rstart + rcnt + pad;
            }
        }
        if (pass == 0) {
            entc = ent; runsc = runs;
            int ei = entc, ri = runsc;
            #pragma unroll
            for (int d = 1; d < 32; d <<= 1) {
                int v = __shfl_up_sync(0xffffffffu, ei, d);
                int u = __shfl_up_sync(0xffffffffu, ri, d);
                if (lane >= d) { ei += v; ri += u; }
            }
            wabs  = t * WSLOT + (ei - entc);
            rbase = ri - runsc;
            if (lane == 31) g_rcnt[t] = min(ri, RSLOT);
        }
    }
}

// ---------------------------------------------------------------------------
// Stage 1: gather with rolling column window. Writes z M-major g_z[m][ck],
// tf32-RN-rounded for the mma stage (accumulation itself stays fp32-exact).
// ---------------------------------------------------------------------------
__global__ void __launch_bounds__(256, 2)
gather_kernel() {
    const int tid  = threadIdx.x;
    const int warp = tid >> 5;
    const int lane = tid & 31;

    const int yb = blockIdx.y;
    const int t  = (yb & 1) ? (NLAT - 1 - (yb >> 1)) : (yb >> 1);   // pole-first
    const int b  = blockIdx.z;
    const int p0 = blockIdx.x * PT;
    const int pbase = p0 + warp * 4;

    const int nruns = g_rcnt[t];
    const int4* runs = g_runs + (size_t)t * RSLOT;
    const float4* xb = (const float4*)(g_xt + (size_t)b * CHW * CIN);

    unsigned long long a2[3][4][2];
    #pragma unroll
    for (int k = 0; k < 3; k++)
        #pragma unroll
        for (int q = 0; q < 4; q++) { a2[k][q][0] = 0ull; a2[k][q][1] = 0ull; }

    for (int r = 0; r < nruns; r++) {
        const int4 rn = __ldg(&runs[r]);
        const int la   = rn.x;
        const int cnt  = rn.z;
        const float4* wp = g_rw + rn.w;
        const int rowb = la * NLON;

        int col = rn.y + pbase;
        if (col >= NLON) col -= NLON;
        if (col >= NLON) col -= NLON;
        int c1 = col + 1; if (c1 >= NLON) c1 -= NLON;
        int c2 = c1 + 1;  if (c2 >= NLON) c2 -= NLON;

        F4U w0v, w1v, w2v;
        w0v.f = xb[(size_t)(rowb + col) * 32 + lane];
        w1v.f = xb[(size_t)(rowb + c1)  * 32 + lane];
        w2v.f = xb[(size_t)(rowb + c2)  * 32 + lane];
        int colx = c2;

        for (int j4 = 0; j4 < cnt; j4 += 4) {
            int n0 = colx + 1; if (n0 >= NLON) n0 -= NLON;
            int n1 = n0 + 1;   if (n1 >= NLON) n1 -= NLON;
            int n2 = n1 + 1;   if (n2 >= NLON) n2 -= NLON;
            int n3 = n2 + 1;   if (n3 >= NLON) n3 -= NLON;
            colx = n3;
            F4U nw0, nw1, nw2, nw3;
            nw0.f = xb[(size_t)(rowb + n0) * 32 + lane];
            nw1.f = xb[(size_t)(rowb + n1) * 32 + lane];
            nw2.f = xb[(size_t)(rowb + n2) * 32 + lane];
            nw3.f = xb[(size_t)(rowb + n3) * 32 + lane];

            float4 wa = __ldg(&wp[j4 + 0]);
            float4 wb = __ldg(&wp[j4 + 1]);
            float4 wc = __ldg(&wp[j4 + 2]);
            float4 wd = __ldg(&wp[j4 + 3]);

            #define DO_ENTRY(W, V0, V1, V2, V3)                                   \
            {                                                                     \
                unsigned long long k0 = pack2(W.x, W.x);                          \
                unsigned long long k1 = pack2(W.y, W.y);                          \
                unsigned long long k2 = pack2(W.z, W.z);                          \
                fma2(a2[0][0][0], k0, V0.u[0]); fma2(a2[0][0][1], k0, V0.u[1]);   \
                fma2(a2[1][0][0], k1, V0.u[0]); fma2(a2[1][0][1], k1, V0.u[1]);   \
                fma2(a2[2][0][0], k2, V0.u[0]); fma2(a2[2][0][1], k2, V0.u[1]);   \
                fma2(a2[0][1][0], k0, V1.u[0]); fma2(a2[0][1][1], k0, V1.u[1]);   \
                fma2(a2[1][1][0], k1, V1.u[0]); fma2(a2[1][1][1], k1, V1.u[1]);   \
                fma2(a2[2][1][0], k2, V1.u[0]); fma2(a2[2][1][1], k2, V1.u[1]);   \
                fma2(a2[0][2][0], k0, V2.u[0]); fma2(a2[0][2][1], k0, V2.u[1]);   \
                fma2(a2[1][2][0], k1, V2.u[0]); fma2(a2[1][2][1], k1, V2.u[1]);   \
                fma2(a2[2][2][0], k2, V2.u[0]); fma2(a2[2][2][1], k2, V2.u[1]);   \
                fma2(a2[0][3][0], k0, V3.u[0]); fma2(a2[0][3][1], k0, V3.u[1]);   \
                fma2(a2[1][3][0], k1, V3.u[0]); fma2(a2[1][3][1], k1, V3.u[1]);   \
                fma2(a2[2][3][0], k2, V3.u[0]); fma2(a2[2][3][1], k2, V3.u[1]);   \
            }
            DO_ENTRY(wa, w0v, w1v, w2v, nw0)
            DO_ENTRY(wb, w1v, w2v, nw0, nw1)
            DO_ENTRY(wc, w2v, nw0, nw1, nw2)
            DO_ENTRY(wd, nw0, nw1, nw2, nw3)
            #undef DO_ENTRY
            w0v = nw1; w1v = nw2; w2v = nw3;
        }
    }

    // store z[m][ck] (tf32-rounded): ck = (lane*4 + c)*3 + k
    if (pbase < NLON) {
        const size_t mb = (size_t)(b * NLAT + t) * NLON + pbase;
        #pragma unroll
        for (int q = 0; q < 4; q++) {
            float* zp = g_z + (mb + q) * (size_t)CK + lane * 12;
            U2F x00, x10, x20, x01, x11, x21;
            x00.u = a2[0][q][0]; x10.u = a2[1][q][0]; x20.u = a2[2][q][0];
            x01.u = a2[0][q][1]; x11.u = a2[1][q][1]; x21.u = a2[2][q][1];
            *(float4*)(zp + 0) = make_float4(tf32r(x00.f.x), tf32r(x10.f.x),
                                             tf32r(x20.f.x), tf32r(x00.f.y));
            *(float4*)(zp + 4) = make_float4(tf32r(x10.f.y), tf32r(x20.f.y),
                                             tf32r(x01.f.x), tf32r(x11.f.x));
            *(float4*)(zp + 8) = make_float4(tf32r(x21.f.x), tf32r(x01.f.y),
                                             tf32r(x11.f.y), tf32r(x21.f.y));
        }
    }
}

// ---------------------------------------------------------------------------
// Stage 2: mma.sync tf32 GEMM. Per CTA: D[128m x 128f] = z[128m x 384] @ W^T.
// cp.async double-buffered smem (12 chunks of K=32), warps 4m x 2f,
// per-warp 2x8 m16n8k8 tiles, fp32 accum, bias + direct coalesced stores.
// ---------------------------------------------------------------------------
__global__ void __launch_bounds__(256)
gemm_mma_kernel(const float* __restrict__ bias, float* __restrict__ out) {
    extern __shared__ float smem[];     // [2][ (A:128*36) + (B:128*36) ]
    __shared__ float s_bias[COUT];

    const int tid  = threadIdx.x;
    const int warp = tid >> 5;
    const int lane = tid & 31;
    const int g    = lane >> 2;         // fragment group row
    const int tg   = lane & 3;          // thread-in-group
    const int wm   = warp & 3;          // m-warp (4 x 32 rows)
    const int wn   = warp >> 2;         // f-warp (2 x 64 cols)
    const int m0   = blockIdx.x * MTILE;

    const uint32_t sbase = smem_u32(smem);
    const int lr = tid >> 3;            // load row group 0..31
    const int lc = tid & 7;             // float4 col 0..7

    if (tid < COUT) s_bias[tid] = __ldg(bias + tid);

    float acc[2][8][4];
    #pragma unroll
    for (int mt = 0; mt < 2; mt++)
        #pragma unroll
        for (int nt = 0; nt < 8; nt++)
            #pragma unroll
            for (int i = 0; i < 4; i++) acc[mt][nt][i] = 0.f;

    // chunk loader: A rows from g_z, B rows from g_wtf
    #define LOAD_CHUNK(CH, BUFI)                                                   \
    {                                                                              \
        const uint32_t sa = sbase + (uint32_t)(BUFI) * (2 * 128 * SROW * 4);       \
        const uint32_t sb = sa + 128 * SROW * 4;                                   \
        _Pragma("unroll")                                                          \
        for (int i = 0; i < 4; i++) {                                              \
            const int row = lr + i * 32;                                           \
            const uint32_t so = (uint32_t)(row * SROW + lc * 4) * 4;               \
            cpasync16(sa + so, &g_z[(size_t)(m0 + row) * CK + (CH) * KCH + lc * 4]); \
            cpasync16(sb + so, &g_wtf[row * CK + (CH) * KCH + lc * 4]);            \
        }                                                                          \
        cp_commit();                                                               \
    }

    LOAD_CHUNK(0, 0)

    for (int ch = 0; ch < NCH; ch++) {
        if (ch + 1 < NCH) { LOAD_CHUNK(ch + 1, (ch + 1) & 1) }
        if (ch + 1 < NCH) cp_wait<1>(); else cp_wait<0>();
        __syncthreads();

        const float* sA = smem + (ch & 1) * (2 * 128 * SROW);
        const float* sB = sA + 128 * SROW;

        #pragma unroll
        for (int ks = 0; ks < 4; ks++) {
            const int k0 = ks * 8;
            uint32_t afr[2][4];
            #pragma unroll
            for (int mt = 0; mt < 2; mt++) {
                const int mb = wm * 32 + mt * 16;
                afr[mt][0] = __float_as_uint(sA[(mb + g)     * SROW + k0 + tg]);
                afr[mt][1] = __float_as_uint(sA[(mb + g + 8) * SROW + k0 + tg]);
                afr[mt][2] = __float_as_uint(sA[(mb + g)     * SROW + k0 + tg + 4]);
                afr[mt][3] = __float_as_uint(sA[(mb + g + 8) * SROW + k0 + tg + 4]);
            }
            #pragma unroll
            for (int nt = 0; nt < 8; nt++) {
                const int nb = wn * 64 + nt * 8;
                const uint32_t b0 = __float_as_uint(sB[(nb + g) * SROW + k0 + tg]);
                const uint32_t b1 = __float_as_uint(sB[(nb + g) * SROW + k0 + tg + 4]);
                mma_tf32(acc[0][nt], afr[0], b0, b1);
                mma_tf32(acc[1][nt], afr[1], b0, b1);
            }
        }
        __syncthreads();
    }

    // Epilogue: D[m][f] -> out[b][f][t][p] with bias.
    #pragma unroll
    for (int mt = 0; mt < 2; mt++) {
        const int mlo = m0 + wm * 32 + mt * 16 + g;
        const int mhi = mlo + 8;
        const bool vlo = (mlo < MTOT), vhi = (mhi < MTOT);
        float* plo = nullptr;
        float* phi = nullptr;
        if (vlo) { int bb = mlo / CHW; plo = out + (size_t)bb * COUT * CHW + (mlo - bb * CHW); }
        if (vhi) { int bb = mhi / CHW; phi = out + (size_t)bb * COUT * CHW + (mhi - bb * CHW); }
        #pragma unroll
        for (int nt = 0; nt < 8; nt++) {
            const int f0 = wn * 64 + nt * 8 + tg * 2;
            const float b0 = s_bias[f0], b1 = s_bias[f0 + 1];
            if (vlo) {
                plo[(size_t)f0 * CHW]       = acc[mt][nt][0] + b0;
                plo[(size_t)(f0 + 1) * CHW] = acc[mt][nt][1] + b1;
            }
            if (vhi) {
                phi[(size_t)f0 * CHW]       = acc[mt][nt][2] + b0;
                phi[(size_t)(f0 + 1) * CHW] = acc[mt][nt][3] + b1;
            }
        }
    }
    #undef LOAD_CHUNK
}

// ---------------------------------------------------------------------------
// Launch.
// ---------------------------------------------------------------------------
extern "C" void kernel_launch(void* const* d_in, const int* in_sizes, int n_in,
                              void* d_out, int out_size) {
    const float* x      = (const float*)d_in[0];
    const float* qw     = (const float*)d_in[1];
    const float* vals   = (const float*)d_in[2];
    const float* weight = (const float*)d_in[3];
    const float* bias   = (const float*)d_in[4];
    const int*   seg    = (const int*)d_in[5];
    const int*   lat    = (const int*)d_in[6];
    const int*   lon    = (const int*)d_in[7];
    const int    nnz    = in_sizes[2];

    dim3 tgrid((CHW + 31) / 32, CIN / 32, BSZ);
    transpose_kernel<<<tgrid, dim3(32, 8)>>>(x);
    wconv_kernel<<<(COUT * CK + 255) / 256, 256>>>(weight);
    merge_kernel<<<(NLAT * 32 + 127) / 128, 128>>>(seg, lat, lon, vals, qw, nnz);

    dim3 ggrid(NPT, NLAT, BSZ);
    gather_kernel<<<ggrid, 256>>>();

    const int dyn_bytes = 2 * 2 * 128 * SROW * sizeof(float);   // 73728
    cudaFuncSetAttribute(gemm_mma_kernel,
                         cudaFuncAttributeMaxDynamicSharedMemorySize, dyn_bytes);
    gemm_mma_kernel<<<MBLK, 256, dyn_bytes>>>(bias, (float*)d_out);
}